// round 15
// baseline (speedup 1.0000x reference)
#include <cuda_runtime.h>
#include <cuda_bf16.h>
#include <cuda_fp16.h>
#include <cstdint>

#define D_MODEL 2048
#define N_HEADS 16
#define D_FF    8192
#define BB      4
#define TT      1024
#define BT      (BB*TT)      // 4096 tokens
#define DH      128
#define BH      (BB*N_HEADS) // 64

// ---------------- scratch (device globals; no allocs allowed) ----------------
__device__ float g_x1 [(long)BT*D_MODEL];   // residual after O proj
__device__ float g_s6 [3*D_MODEL];          // concatenated q/k/v scales

// fp16 tensors
__device__ __align__(16) __half g_hd [(long)BT*D_MODEL];   // activations (d_model)
__device__ __align__(16) __half g_hf [(long)BT*D_FF];      // post-gelu activations
__device__ __align__(16) __half g_ffa[(long)BT*D_FF];      // pre-gelu FF1 out
__device__ __align__(16) __half g_qh [(long)BT*D_MODEL];   // q [b,h,t,d]
__device__ __align__(16) __half g_kh [(long)BT*D_MODEL];   // k [b,h,t,d]
__device__ __align__(16) __half g_vth[(long)BT*D_MODEL];   // v [b,h,d,t]
__device__ __align__(16) __half g_ath[(long)BT*D_MODEL];   // attn out fp16 [b,t,h*d]

// fp16 weights (int8 values exact in fp16); q,k,v contiguous; o,f1,f2 contiguous
#define NWD ((long)D_MODEL*D_MODEL)   // 4,194,304
#define NWF ((long)D_FF*D_MODEL)      // 16,777,216
__device__ __align__(16) __half g_w[(long)4*NWD + 2*NWF];
__device__ int g_cnt32;
__device__ int g_cntf;

// ---------------- dtype probe + weight normalization ----------------
__global__ void zero_counters() { g_cnt32 = 0; g_cntf = 0; }

__global__ void probe_dtype(const void* __restrict__ p, int nwords)
{
    int i = blockIdx.x * blockDim.x + threadIdx.x;
    if (i >= nwords) return;
    int v = ((const int*)p)[i];
    if (v < -127 || v > 127) atomicAdd(&g_cnt32, 1);
    float f = ((const float*)p)[i];
    bool okf = (f >= -127.0f) && (f <= 127.0f) && (f == rintf(f));
    if (!okf) atomicAdd(&g_cntf, 1);
}

__device__ __forceinline__ void conv4(const void* __restrict__ src, long j, __half2* __restrict__ dst2, long o)
{
    int mode = (g_cnt32 == 0) ? 1 : ((g_cntf == 0) ? 2 : 0);  // 1=int32, 2=float32, 0=int8
    float f0, f1, f2, f3;
    if (mode == 1) {
        int4 v = ((const int4*)src)[j];
        f0 = (float)v.x; f1 = (float)v.y; f2 = (float)v.z; f3 = (float)v.w;
    } else if (mode == 2) {
        float4 v = ((const float4*)src)[j];
        f0 = rintf(v.x); f1 = rintf(v.y); f2 = rintf(v.z); f3 = rintf(v.w);
    } else {
        char4 v = ((const char4*)src)[j];
        f0 = (float)v.x; f1 = (float)v.y; f2 = (float)v.z; f3 = (float)v.w;
    }
    dst2[2 * o]     = __floats2half2_rn(f0, f1);
    dst2[2 * o + 1] = __floats2half2_rn(f2, f3);
}

// q,k,v -> contiguous wqkv
__global__ void convert_w3(const void* __restrict__ s0, const void* __restrict__ s1,
                           const void* __restrict__ s2, __half* __restrict__ dst, long n4)
{
    long i = (long)blockIdx.x * blockDim.x + threadIdx.x;
    if (i >= 3 * n4) return;
    int which = (int)(i / n4);
    long j = i % n4;
    const void* src = (which == 0) ? s0 : ((which == 1) ? s1 : s2);
    conv4(src, j, (__half2*)dst, i);
}

// o (NWD) + f1 (NWF) + f2 (NWF) -> contiguous region starting at wo
__global__ void convert_rest(const void* __restrict__ s0, const void* __restrict__ s1,
                             const void* __restrict__ s2, __half* __restrict__ dst,
                             long n4o, long n4f)
{
    long i = (long)blockIdx.x * blockDim.x + threadIdx.x;
    if (i >= n4o + 2 * n4f) return;
    const void* src;
    long j;
    if (i < n4o)            { src = s0; j = i; }
    else if (i < n4o + n4f) { src = s1; j = i - n4o; }
    else                    { src = s2; j = i - n4o - n4f; }
    conv4(src, j, (__half2*)dst, i);
}

__global__ void cat_scales(const float* __restrict__ a, const float* __restrict__ b,
                           const float* __restrict__ c, float* __restrict__ d)
{
    int i = blockIdx.x * blockDim.x + threadIdx.x;
    if (i >= 3 * D_MODEL) return;
    d[i] = (i < D_MODEL) ? a[i] : ((i < 2 * D_MODEL) ? b[i - D_MODEL] : c[i - 2 * D_MODEL]);
}

// ---------------- mma / ldmatrix / cp.async helpers ----------------
__device__ __forceinline__ void ldsm_x4(uint32_t& r0, uint32_t& r1, uint32_t& r2, uint32_t& r3, uint32_t a) {
    asm volatile("ldmatrix.sync.aligned.m8n8.x4.shared.b16 {%0,%1,%2,%3},[%4];"
                 : "=r"(r0), "=r"(r1), "=r"(r2), "=r"(r3) : "r"(a));
}
__device__ __forceinline__ void mma16816h(float* c, uint32_t a0, uint32_t a1, uint32_t a2, uint32_t a3,
                                          uint32_t b0, uint32_t b1) {
    asm volatile("mma.sync.aligned.m16n8k16.row.col.f32.f16.f16.f32 "
                 "{%0,%1,%2,%3},{%4,%5,%6,%7},{%8,%9},{%0,%1,%2,%3};"
                 : "+f"(c[0]), "+f"(c[1]), "+f"(c[2]), "+f"(c[3])
                 : "r"(a0), "r"(a1), "r"(a2), "r"(a3), "r"(b0), "r"(b1));
}
__device__ __forceinline__ void cp16(uint32_t dst, const void* src) {
    asm volatile("cp.async.cg.shared.global [%0], [%1], 16;"
                 :: "r"(dst), "l"(__cvta_generic_to_global(src)) : "memory");
}
__device__ __forceinline__ uint32_t smem_u32(const void* p) {
    uint32_t a;
    asm("{ .reg .u64 t; cvta.to.shared.u64 t, %1; cvt.u32.u64 %0, t; }" : "=r"(a) : "l"(p));
    return a;
}

#define STB    32768                  // bytes per stage (A 16K + B 16K)
#define SMEM_G (3*STB)                // 98304 -> 2 CTAs/SM co-residency

// ============================================================================
// GEMM-H (fp16, cp.async 3-stage pipeline, tile 128x128, 2 CTA/SM)
// CTA raster swizzled: GROUP_M=8 m-blocks per n-sweep for L2 reuse.
// B fragments loaded as paired ldsm_x4 (2 n-tiles per load).
// LAYOUT: 0 = fp32 o0[r*ldc+c]
//         3 = merged QKV -> fp16 q(o0)/k(o1)/V^T(o2) head layouts
//         4 = fp16 o0[r*ldc+c]
// ============================================================================
template<int LAYOUT, bool HAS_BIAS, bool HAS_RES>
__global__ void __launch_bounds__(256) gemm_h(
    const __half* __restrict__ A, const __half* __restrict__ W, int K,
    const float* __restrict__ s, const float* __restrict__ bias,
    const float* __restrict__ res, void* __restrict__ o0,
    void* __restrict__ o1, void* __restrict__ o2, int ldc)
{
    extern __shared__ char smem[];
    const uint32_t sb = smem_u32(smem);
    const int tid = threadIdx.x, lane = tid & 31, w = tid >> 5;
    const int wm = w & 1, wn = w >> 1;

    // ---- swizzled CTA raster: groups of 8 m-blocks, n varies slowest ----
    const int gx = gridDim.x;
    const int bid = blockIdx.y * gx + blockIdx.x;
    const int grp = bid / (8 * gx), rem = bid % (8 * gx);
    const int m0 = (grp * 8 + (rem & 7)) * 128;
    const int n0 = (rem >> 3) * 128;
    const int KB = K >> 6;

    const __half* Ag = A + (long)m0 * K;
    const __half* Bg = W + (long)n0 * K;

    const int lr = tid >> 3, lj = tid & 7;

    auto load_stage = [&](int st, int kb) {
        const __half* a = Ag + kb * 64;
        const __half* b = Bg + kb * 64;
        #pragma unroll
        for (int i = 0; i < 4; i++) {
            int r = lr + i * 32;
            uint32_t dsw = r * 128 + ((lj ^ (r & 7)) * 16);
            cp16(sb + st * STB + dsw, a + (long)r * K + lj * 8);
        }
        #pragma unroll
        for (int i = 0; i < 4; i++) {
            int r = lr + i * 32;
            uint32_t dsw = r * 128 + ((lj ^ (r & 7)) * 16);
            cp16(sb + st * STB + 16384 + dsw, b + (long)r * K + lj * 8);
        }
        asm volatile("cp.async.commit_group;" ::: "memory");
    };

    float acc[4][4][4];
    #pragma unroll
    for (int i = 0; i < 4; i++)
        #pragma unroll
        for (int j = 0; j < 4; j++)
            #pragma unroll
            for (int e = 0; e < 4; e++) acc[i][j][e] = 0.f;

    load_stage(0, 0);
    if (KB > 1) load_stage(1, 1);

    for (int kb = 0; kb < KB; kb++) {
        const int st = kb % 3;
        if (kb + 1 < KB) { asm volatile("cp.async.wait_group 1;" ::: "memory"); }
        else             { asm volatile("cp.async.wait_group 0;" ::: "memory"); }
        __syncthreads();
        if (kb + 2 < KB) load_stage((kb + 2) % 3, kb + 2);

        const uint32_t aB = sb + st * STB, bB = sb + st * STB + 16384;
        #pragma unroll
        for (int ks = 0; ks < 4; ks++) {
            const int kk = ks * 16 + (lane >> 4) * 8;
            uint32_t af[4][4];
            #pragma unroll
            for (int i = 0; i < 4; i++) {
                int ra = wm * 64 + i * 16 + (lane & 15);
                uint32_t ad = aB + ra * 128 + (((kk >> 3) ^ (ra & 7)) * 16);
                ldsm_x4(af[i][0], af[i][1], af[i][2], af[i][3], ad);
            }
            #pragma unroll
            for (int jj = 0; jj < 2; jj++) {
                int rb = wn * 32 + jj * 16 + (lane & 15);
                uint32_t bd = bB + rb * 128 + (((kk >> 3) ^ (rb & 7)) * 16);
                uint32_t r0, r1, r2, r3;
                ldsm_x4(r0, r1, r2, r3, bd);
                #pragma unroll
                for (int i = 0; i < 4; i++) {
                    mma16816h(acc[i][2 * jj],     af[i][0], af[i][1], af[i][2], af[i][3], r0, r2);
                    mma16816h(acc[i][2 * jj + 1], af[i][0], af[i][1], af[i][2], af[i][3], r1, r3);
                }
            }
        }
    }

    // --- epilogue ---
    const int gr = lane >> 2, gc = (lane & 3) * 2;
    #pragma unroll
    for (int i = 0; i < 4; i++) {
        #pragma unroll
        for (int j = 0; j < 4; j++) {
            int rbase = m0 + wm * 64 + i * 16 + gr;
            int cbase = n0 + wn * 32 + j * 8 + gc;
            #pragma unroll
            for (int e = 0; e < 4; e++) {
                int r = rbase + (e >> 1) * 8;
                int c = cbase + (e & 1);
                float v = acc[i][j][e] * s[c];
                if (HAS_BIAS) v += bias[c];
                if (HAS_RES)  v += res[(long)r * D_MODEL + c];
                if (LAYOUT == 0) {
                    ((float*)o0)[(long)r * ldc + c] = v;
                } else if (LAYOUT == 4) {
                    ((__half*)o0)[(long)r * ldc + c] = __float2half_rn(v);
                } else {
                    int b = r >> 10, t = r & 1023;
                    int mat = c >> 11, cc = c & 2047;
                    int h = cc >> 7, d = cc & 127;
                    long base = (long)(b * N_HEADS + h) * (TT * DH);
                    long idx = base + ((mat == 2) ? ((long)d * TT + t) : ((long)t * DH + d));
                    __half* o = (mat == 0) ? (__half*)o0 : ((mat == 1) ? (__half*)o1 : (__half*)o2);
                    o[idx] = __float2half_rn(v);
                }
            }
        }
    }
}

// ============================================================================
// Flash attention v2: 8 warps x 16 q-rows, full key width per warp.
// P stays in registers; softmax warp-local (shfl only).
// ============================================================================
#define FA_RSB 272
#define FA_Q   0
#define FA_K0  34816
#define FA_K1  69632
#define FA_V   104448
#define SMEM_FA 139264

__global__ void __launch_bounds__(256) flash_attn(
    const __half* __restrict__ qh, const __half* __restrict__ kh,
    const __half* __restrict__ vth, __half* __restrict__ ath)
{
    extern __shared__ char smem[];
    const uint32_t sb = smem_u32(smem);
    const int tid = threadIdx.x, lane = tid & 31, w = tid >> 5;
    const int gr = lane >> 2, gc = (lane & 3) * 2;
    const int qt = blockIdx.x, z = blockIdx.y;

    const __half* Qg = qh  + (long)z * TT * DH + (long)qt * 128 * DH;
    const __half* Kg = kh  + (long)z * TT * DH;
    const __half* Vg = vth + (long)z * TT * DH;

    auto load_tile = [&](uint32_t off, const __half* src, int ldg) {
        #pragma unroll
        for (int i = 0; i < 8; i++) {
            int c = tid + i * 256;
            int r = c >> 4, ch = c & 15;
            cp16(sb + off + r * FA_RSB + ch * 16, src + (long)r * ldg + ch * 8);
        }
        asm volatile("cp.async.commit_group;" ::: "memory");
    };

    load_tile(FA_Q, Qg, DH);
    load_tile(FA_K0, Kg, DH);

    float oacc[16][4];
    float m2[2], l2[2];
    #pragma unroll
    for (int j = 0; j < 16; j++)
        #pragma unroll
        for (int e = 0; e < 4; e++) oacc[j][e] = 0.f;
    m2[0] = m2[1] = -1e30f;
    l2[0] = l2[1] = 0.f;

    const int ra = w * 16 + (lane & 15);

    for (int kt = 0; kt < 8; kt++) {
        __syncthreads();
        load_tile(FA_V, Vg + kt * 128, TT);
        if (kt < 7) load_tile((kt & 1) ? FA_K0 : FA_K1, Kg + (long)(kt + 1) * 128 * DH, DH);
        if (kt < 7) { asm volatile("cp.async.wait_group 1;" ::: "memory"); }
        else        { asm volatile("cp.async.wait_group 0;" ::: "memory"); }
        __syncthreads();

        const uint32_t kOff = sb + ((kt & 1) ? FA_K1 : FA_K0);
        float sacc[16][4];
        #pragma unroll
        for (int j = 0; j < 16; j++)
            #pragma unroll
            for (int e = 0; e < 4; e++) sacc[j][e] = 0.f;
        #pragma unroll
        for (int ks = 0; ks < 8; ks++) {
            const int kk = ks * 16 + (lane >> 4) * 8;
            uint32_t a0, a1, a2, a3;
            ldsm_x4(a0, a1, a2, a3, sb + FA_Q + ra * FA_RSB + kk * 2);
            #pragma unroll
            for (int jj = 0; jj < 8; jj++) {
                uint32_t r0, r1, r2, r3;
                ldsm_x4(r0, r1, r2, r3, kOff + (jj * 16 + (lane & 15)) * FA_RSB + kk * 2);
                mma16816h(sacc[2 * jj],     a0, a1, a2, a3, r0, r2);
                mma16816h(sacc[2 * jj + 1], a0, a1, a2, a3, r1, r3);
            }
        }
        #pragma unroll
        for (int j = 0; j < 16; j++)
            #pragma unroll
            for (int e = 0; e < 4; e++) sacc[j][e] *= 0.08838834764831845f;

        float tmx[2];
        tmx[0] = -1e30f; tmx[1] = -1e30f;
        #pragma unroll
        for (int j = 0; j < 16; j++) {
            tmx[0] = fmaxf(tmx[0], fmaxf(sacc[j][0], sacc[j][1]));
            tmx[1] = fmaxf(tmx[1], fmaxf(sacc[j][2], sacc[j][3]));
        }
        #pragma unroll
        for (int s = 0; s < 2; s++) {
            tmx[s] = fmaxf(tmx[s], __shfl_xor_sync(0xffffffffu, tmx[s], 1));
            tmx[s] = fmaxf(tmx[s], __shfl_xor_sync(0xffffffffu, tmx[s], 2));
        }
        float f2[2];
        #pragma unroll
        for (int s = 0; s < 2; s++) {
            float mn = fmaxf(m2[s], tmx[s]);
            f2[s] = __expf(m2[s] - mn);
            m2[s] = mn;
        }
        float tsm[2];
        tsm[0] = 0.f; tsm[1] = 0.f;
        #pragma unroll
        for (int j = 0; j < 16; j++) {
            float p0 = __expf(sacc[j][0] - m2[0]);
            float p1 = __expf(sacc[j][1] - m2[0]);
            float p2 = __expf(sacc[j][2] - m2[1]);
            float p3 = __expf(sacc[j][3] - m2[1]);
            sacc[j][0] = p0; sacc[j][1] = p1; sacc[j][2] = p2; sacc[j][3] = p3;
            tsm[0] += p0 + p1;
            tsm[1] += p2 + p3;
        }
        #pragma unroll
        for (int s = 0; s < 2; s++) {
            tsm[s] += __shfl_xor_sync(0xffffffffu, tsm[s], 1);
            tsm[s] += __shfl_xor_sync(0xffffffffu, tsm[s], 2);
            l2[s] = l2[s] * f2[s] + tsm[s];
        }
        #pragma unroll
        for (int j = 0; j < 16; j++) {
            oacc[j][0] *= f2[0]; oacc[j][1] *= f2[0];
            oacc[j][2] *= f2[1]; oacc[j][3] *= f2[1];
        }

        uint32_t pf[8][4];
        #pragma unroll
        for (int ks = 0; ks < 8; ks++) {
            __half2 h0 = __floats2half2_rn(sacc[2 * ks][0],     sacc[2 * ks][1]);
            __half2 h1 = __floats2half2_rn(sacc[2 * ks][2],     sacc[2 * ks][3]);
            __half2 h2 = __floats2half2_rn(sacc[2 * ks + 1][0], sacc[2 * ks + 1][1]);
            __half2 h3 = __floats2half2_rn(sacc[2 * ks + 1][2], sacc[2 * ks + 1][3]);
            pf[ks][0] = *(uint32_t*)&h0;
            pf[ks][1] = *(uint32_t*)&h1;
            pf[ks][2] = *(uint32_t*)&h2;
            pf[ks][3] = *(uint32_t*)&h3;
        }

        #pragma unroll
        for (int ks = 0; ks < 8; ks++) {
            const int kk = ks * 16 + (lane >> 4) * 8;
            #pragma unroll
            for (int jj = 0; jj < 8; jj++) {
                uint32_t r0, r1, r2, r3;
                ldsm_x4(r0, r1, r2, r3, sb + FA_V + (jj * 16 + (lane & 15)) * FA_RSB + kk * 2);
                mma16816h(oacc[2 * jj],     pf[ks][0], pf[ks][1], pf[ks][2], pf[ks][3], r0, r2);
                mma16816h(oacc[2 * jj + 1], pf[ks][0], pf[ks][1], pf[ks][2], pf[ks][3], r1, r3);
            }
        }
    }

    float inv2[2];
    inv2[0] = 1.0f / l2[0];
    inv2[1] = 1.0f / l2[1];
    const int b = z >> 4, hh = z & 15;
    #pragma unroll
    for (int j = 0; j < 16; j++)
        #pragma unroll
        for (int e = 0; e < 4; e++) {
            int s = e >> 1;
            int t = qt * 128 + w * 16 + gr + s * 8;
            int d = j * 8 + gc + (e & 1);
            ath[((long)(b * TT + t)) * D_MODEL + hh * DH + d] =
                __float2half_rn(oacc[j][e] * inv2[s]);
        }
}

// ---------------- reductions ----------------
__device__ __forceinline__ float warp_sum(float v) {
    #pragma unroll
    for (int o = 16; o; o >>= 1) v += __shfl_xor_sync(0xffffffffu, v, o);
    return v;
}
template<int NW>
__device__ __forceinline__ float block_sum(float v, float* buf) {
    int tid = threadIdx.x;
    v = warp_sum(v);
    __syncthreads();
    if ((tid & 31) == 0) buf[tid >> 5] = v;
    __syncthreads();
    if (tid == 0) { float t = 0; for (int i = 0; i < NW; i++) t += buf[i]; buf[0] = t; }
    __syncthreads();
    return buf[0];
}

// in-register butterfly over NB low bits of the register index
template<int NR, int NB>
__device__ __forceinline__ void reg_butterfly(float* v) {
    #pragma unroll
    for (int b = 0; b < NB; b++) {
        int hb = 1 << b;
        #pragma unroll
        for (int j = 0; j < NR; j++) {
            if (!(j & hb)) {
                float a = v[j], c = v[j | hb];
                v[j] = a + c;
                v[j | hb] = a - c;
            }
        }
    }
}
// shfl butterfly over lane bits 0..4
template<int NR>
__device__ __forceinline__ void shfl_butterfly(float* v, int lane) {
    #pragma unroll
    for (int m = 1; m <= 16; m <<= 1) {
        #pragma unroll
        for (int j = 0; j < NR; j++) {
            float other = __shfl_xor_sync(0xffffffffu, v[j], m);
            v[j] = (lane & m) ? (other - v[j]) : (v[j] + other);
        }
    }
}

// ------- LN (optional) + Hadamard-2048 -> fp16 (register/shfl butterfly) -------
template<bool DO_LN, typename TIN>
__global__ void __launch_bounds__(256) ln_had2048(
    const TIN* __restrict__ in, const float* __restrict__ g,
    const float* __restrict__ bta, __half* __restrict__ outs)
{
    __shared__ float s[2048];
    __shared__ float red[8];
    const int tid = threadIdx.x, lane = tid & 31, w = tid >> 5;
    const TIN* x = in + (long)blockIdx.x * 2048;
    float loc[8];
    #pragma unroll
    for (int j = 0; j < 8; j++) loc[j] = (float)x[tid + 256 * j];

    if (DO_LN) {
        float sm = 0.f, sq = 0.f;
        #pragma unroll
        for (int j = 0; j < 8; j++) { sm += loc[j]; sq += loc[j] * loc[j]; }
        float S  = block_sum<8>(sm, red);
        float SQ = block_sum<8>(sq, red);
        float mu = S * (1.0f / 2048.0f);
        float var = SQ * (1.0f / 2048.0f) - mu * mu;
        float inv = rsqrtf(var + 1e-5f);
        #pragma unroll
        for (int j = 0; j < 8; j++) {
            int c = tid + 256 * j;
            loc[j] = (loc[j] - mu) * inv * g[c] + bta[c];
        }
    }

    reg_butterfly<8, 3>(loc);            // bits 8-10
    #pragma unroll
    for (int j = 0; j < 8; j++) s[tid + 256 * j] = loc[j];
    __syncthreads();
    float v[8];
    #pragma unroll
    for (int jj = 0; jj < 8; jj++) v[jj] = s[lane + 32 * jj + 256 * w];
    reg_butterfly<8, 3>(v);              // bits 5-7
    shfl_butterfly<8>(v, lane);          // bits 0-4

    __half* o = outs + (long)blockIdx.x * 2048;
    #pragma unroll
    for (int jj = 0; jj < 8; jj++)
        o[lane + 32 * jj + 256 * w] = __float2half_rn(v[jj] * 0.022097086912079608f);
}

// ------- GELU(exact) + Hadamard-8192 (fp16 in) -> fp16 (register/shfl) -------
__global__ void __launch_bounds__(512) gelu_had8192(const __half* __restrict__ in, __half* __restrict__ outs)
{
    __shared__ float s[8192];
    const int tid = threadIdx.x, lane = tid & 31, w = tid >> 5;
    const __half* x = in + (long)blockIdx.x * 8192;
    float loc[16];
    #pragma unroll
    for (int j = 0; j < 16; j++) {
        float v = (float)x[tid + 512 * j];
        loc[j] = 0.5f * v * (1.0f + erff(v * 0.7071067811865476f));
    }

    reg_butterfly<16, 4>(loc);           // bits 9-12
    #pragma unroll
    for (int j = 0; j < 16; j++) s[tid + 512 * j] = loc[j];
    __syncthreads();
    float v[16];
    #pragma unroll
    for (int jj = 0; jj < 16; jj++) v[jj] = s[lane + 32 * jj + 512 * w];
    reg_butterfly<16, 4>(v);             // bits 5-8
    shfl_butterfly<16>(v, lane);         // bits 0-4

    __half* o = outs + (long)blockIdx.x * 8192;
    #pragma unroll
    for (int jj = 0; jj < 16; jj++)
        o[lane + 32 * jj + 512 * w] = __float2half_rn(v[jj] * 0.011048543456039806f);
}

// ============================================================================
extern "C" void kernel_launch(void* const* d_in, const int* in_sizes, int n_in,
                              void* d_out, int out_size)
{
    const float*  x    = (const float*) d_in[0];
    const float*  ln1g = (const float*) d_in[1];
    const float*  ln1b = (const float*) d_in[2];
    const float*  ln2g = (const float*) d_in[3];
    const float*  ln2b = (const float*) d_in[4];
    const void*   Qq   = d_in[5];
    const float*  sq   = (const float*) d_in[6];
    const void*   Qk   = d_in[7];
    const float*  sk   = (const float*) d_in[8];
    const void*   Qv   = d_in[9];
    const float*  sv   = (const float*) d_in[10];
    const void*   Qo   = d_in[11];
    const float*  so   = (const float*) d_in[12];
    const void*   Qf1  = d_in[13];
    const float*  sf1  = (const float*) d_in[14];
    const float*  bf1  = (const float*) d_in[15];
    const void*   Qf2  = d_in[16];
    const float*  sf2  = (const float*) d_in[17];
    const float*  bf2  = (const float*) d_in[18];
    float* out = (float*)d_out;

    float *x1, *s6;
    __half *hd, *hf, *ffa, *qh, *kh, *vth, *ath, *wb;
    cudaGetSymbolAddress((void**)&x1,  g_x1);
    cudaGetSymbolAddress((void**)&s6,  g_s6);
    cudaGetSymbolAddress((void**)&hd,  g_hd);
    cudaGetSymbolAddress((void**)&hf,  g_hf);
    cudaGetSymbolAddress((void**)&ffa, g_ffa);
    cudaGetSymbolAddress((void**)&qh,  g_qh);
    cudaGetSymbolAddress((void**)&kh,  g_kh);
    cudaGetSymbolAddress((void**)&vth, g_vth);
    cudaGetSymbolAddress((void**)&ath, g_ath);
    cudaGetSymbolAddress((void**)&wb,  g_w);

    __half* wqkv = wb;                 // q,k,v contiguous (3*NWD)
    __half* wo   = wb + 3 * NWD;       // o,f1,f2 contiguous (NWD + 2*NWF)
    __half* wf1  = wb + 4 * NWD;
    __half* wf2  = wb + 4 * NWD + NWF;

    cudaFuncSetAttribute((const void*)gemm_h<3, false, false>, cudaFuncAttributeMaxDynamicSharedMemorySize, SMEM_G);
    cudaFuncSetAttribute((const void*)gemm_h<0, false, true>,  cudaFuncAttributeMaxDynamicSharedMemorySize, SMEM_G);
    cudaFuncSetAttribute((const void*)gemm_h<4, true, false>,  cudaFuncAttributeMaxDynamicSharedMemorySize, SMEM_G);
    cudaFuncSetAttribute((const void*)gemm_h<0, true, true>,   cudaFuncAttributeMaxDynamicSharedMemorySize, SMEM_G);
    cudaFuncSetAttribute((const void*)flash_attn,              cudaFuncAttributeMaxDynamicSharedMemorySize, SMEM_FA);

    // dtype probe + weight conversion (front-loaded, 2 launches)
    zero_counters<<<1, 1>>>();
    probe_dtype<<<1024, 256>>>(Qq, 1 << 18);
    convert_w3<<<(int)((3 * (NWD / 4) + 255) / 256), 256>>>(Qq, Qk, Qv, wqkv, NWD / 4);
    convert_rest<<<(int)(((NWD / 4 + 2 * (NWF / 4)) + 255) / 256), 256>>>(Qo, Qf1, Qf2, wo, NWD / 4, NWF / 4);
    cat_scales<<<24, 256>>>(sq, sk, sv, s6);
    // LN1 + Hadamard -> fp16
    ln_had2048<true, float><<<BT, 256>>>(x, ln1g, ln1b, hd);
    // merged QKV projection (N=6144, tile 128x128, 2 CTA/SM)
    gemm_h<3, false, false><<<dim3(48, 32), 256, SMEM_G>>>(hd, wqkv, D_MODEL, s6, nullptr, nullptr, qh, kh, vth, 0);
    // fused attention (scores + softmax + P@V), register-P
    flash_attn<<<dim3(8, BH), 256, SMEM_FA>>>(qh, kh, vth, ath);
    // Hadamard(attn fp16) -> fp16
    ln_had2048<false, __half><<<BT, 256>>>(ath, nullptr, nullptr, hd);
    // O-proj (x1 = x + O-proj), fp32 out
    gemm_h<0, false, true><<<dim3(16, 32), 256, SMEM_G>>>(hd, wo, D_MODEL, so, nullptr, x, x1, nullptr, nullptr, D_MODEL);
    // LN2 + Hadamard -> fp16
    ln_had2048<true, float><<<BT, 256>>>(x1, ln2g, ln2b, hd);
    // FF1 -> fp16 pre-activations
    gemm_h<4, true, false><<<dim3(64, 32), 256, SMEM_G>>>(hd, wf1, D_MODEL, sf1, bf1, nullptr, ffa, nullptr, nullptr, D_FF);
    // GELU + Hadamard-8192 -> fp16
    gelu_had8192<<<BT, 512>>>(ffa, hf);
    // FF2 (out = x1 + FF2), fp32 out
    gemm_h<0, true, true><<<dim3(16, 32), 256, SMEM_G>>>(hf, wf2, D_FF, sf2, bf2, x1, out, nullptr, nullptr, D_MODEL);
}

// round 16
// speedup vs baseline: 1.1732x; 1.1732x over previous
#include <cuda_runtime.h>
#include <cuda_bf16.h>
#include <cuda_fp16.h>
#include <cstdint>

#define D_MODEL 2048
#define N_HEADS 16
#define D_FF    8192
#define BB      4
#define TT      1024
#define BT      (BB*TT)      // 4096 tokens
#define DH      128
#define BH      (BB*N_HEADS) // 64

// ---------------- scratch (device globals; no allocs allowed) ----------------
__device__ float g_x1 [(long)BT*D_MODEL];   // residual after O proj
__device__ float g_s6 [3*D_MODEL];          // concatenated q/k/v scales

// fp16 tensors
__device__ __align__(16) __half g_hd [(long)BT*D_MODEL];   // activations (d_model)
__device__ __align__(16) __half g_hf [(long)BT*D_FF];      // post-gelu activations
__device__ __align__(16) __half g_ffa[(long)BT*D_FF];      // pre-gelu FF1 out
__device__ __align__(16) __half g_qh [(long)BT*D_MODEL];   // q [b,h,t,d]
__device__ __align__(16) __half g_kh [(long)BT*D_MODEL];   // k [b,h,t,d]
__device__ __align__(16) __half g_vth[(long)BT*D_MODEL];   // v [b,h,d,t]
__device__ __align__(16) __half g_ath[(long)BT*D_MODEL];   // attn out fp16 [b,t,h*d]

// fp16 weights (int8 values exact in fp16); q,k,v contiguous; o,f1,f2 contiguous
#define NWD ((long)D_MODEL*D_MODEL)   // 4,194,304
#define NWF ((long)D_FF*D_MODEL)      // 16,777,216
__device__ __align__(16) __half g_w[(long)4*NWD + 2*NWF];
__device__ int g_cnt32;
__device__ int g_cntf;

// ---------------- dtype probe + weight normalization ----------------
__global__ void zero_counters() { g_cnt32 = 0; g_cntf = 0; }

__global__ void probe_dtype(const void* __restrict__ p, int nwords)
{
    int i = blockIdx.x * blockDim.x + threadIdx.x;
    if (i >= nwords) return;
    int v = ((const int*)p)[i];
    if (v < -127 || v > 127) atomicAdd(&g_cnt32, 1);
    float f = ((const float*)p)[i];
    bool okf = (f >= -127.0f) && (f <= 127.0f) && (f == rintf(f));
    if (!okf) atomicAdd(&g_cntf, 1);
}

__device__ __forceinline__ void conv4(const void* __restrict__ src, long j, __half2* __restrict__ dst2, long o)
{
    int mode = (g_cnt32 == 0) ? 1 : ((g_cntf == 0) ? 2 : 0);  // 1=int32, 2=float32, 0=int8
    float f0, f1, f2, f3;
    if (mode == 1) {
        int4 v = ((const int4*)src)[j];
        f0 = (float)v.x; f1 = (float)v.y; f2 = (float)v.z; f3 = (float)v.w;
    } else if (mode == 2) {
        float4 v = ((const float4*)src)[j];
        f0 = rintf(v.x); f1 = rintf(v.y); f2 = rintf(v.z); f3 = rintf(v.w);
    } else {
        char4 v = ((const char4*)src)[j];
        f0 = (float)v.x; f1 = (float)v.y; f2 = (float)v.z; f3 = (float)v.w;
    }
    dst2[2 * o]     = __floats2half2_rn(f0, f1);
    dst2[2 * o + 1] = __floats2half2_rn(f2, f3);
}

// q,k,v -> contiguous wqkv
__global__ void convert_w3(const void* __restrict__ s0, const void* __restrict__ s1,
                           const void* __restrict__ s2, __half* __restrict__ dst, long n4)
{
    long i = (long)blockIdx.x * blockDim.x + threadIdx.x;
    if (i >= 3 * n4) return;
    int which = (int)(i / n4);
    long j = i % n4;
    const void* src = (which == 0) ? s0 : ((which == 1) ? s1 : s2);
    conv4(src, j, (__half2*)dst, i);
}

// o (NWD) + f1 (NWF) + f2 (NWF) -> contiguous region starting at wo
__global__ void convert_rest(const void* __restrict__ s0, const void* __restrict__ s1,
                             const void* __restrict__ s2, __half* __restrict__ dst,
                             long n4o, long n4f)
{
    long i = (long)blockIdx.x * blockDim.x + threadIdx.x;
    if (i >= n4o + 2 * n4f) return;
    const void* src;
    long j;
    if (i < n4o)            { src = s0; j = i; }
    else if (i < n4o + n4f) { src = s1; j = i - n4o; }
    else                    { src = s2; j = i - n4o - n4f; }
    conv4(src, j, (__half2*)dst, i);
}

__global__ void cat_scales(const float* __restrict__ a, const float* __restrict__ b,
                           const float* __restrict__ c, float* __restrict__ d)
{
    int i = blockIdx.x * blockDim.x + threadIdx.x;
    if (i >= 3 * D_MODEL) return;
    d[i] = (i < D_MODEL) ? a[i] : ((i < 2 * D_MODEL) ? b[i - D_MODEL] : c[i - 2 * D_MODEL]);
}

// ---------------- mma / ldmatrix / cp.async helpers ----------------
__device__ __forceinline__ void ldsm_x4(uint32_t& r0, uint32_t& r1, uint32_t& r2, uint32_t& r3, uint32_t a) {
    asm volatile("ldmatrix.sync.aligned.m8n8.x4.shared.b16 {%0,%1,%2,%3},[%4];"
                 : "=r"(r0), "=r"(r1), "=r"(r2), "=r"(r3) : "r"(a));
}
__device__ __forceinline__ void ldsm_x2(uint32_t& r0, uint32_t& r1, uint32_t a) {
    asm volatile("ldmatrix.sync.aligned.m8n8.x2.shared.b16 {%0,%1},[%2];"
                 : "=r"(r0), "=r"(r1) : "r"(a));
}
__device__ __forceinline__ void mma16816h(float* c, uint32_t a0, uint32_t a1, uint32_t a2, uint32_t a3,
                                          uint32_t b0, uint32_t b1) {
    asm volatile("mma.sync.aligned.m16n8k16.row.col.f32.f16.f16.f32 "
                 "{%0,%1,%2,%3},{%4,%5,%6,%7},{%8,%9},{%0,%1,%2,%3};"
                 : "+f"(c[0]), "+f"(c[1]), "+f"(c[2]), "+f"(c[3])
                 : "r"(a0), "r"(a1), "r"(a2), "r"(a3), "r"(b0), "r"(b1));
}
__device__ __forceinline__ void cp16(uint32_t dst, const void* src) {
    asm volatile("cp.async.cg.shared.global [%0], [%1], 16;"
                 :: "r"(dst), "l"(__cvta_generic_to_global(src)) : "memory");
}
__device__ __forceinline__ uint32_t smem_u32(const void* p) {
    uint32_t a;
    asm("{ .reg .u64 t; cvta.to.shared.u64 t, %1; cvt.u32.u64 %0, t; }" : "=r"(a) : "l"(p));
    return a;
}

#define STB    32768                  // bytes per stage (A 16K + B 16K)
#define SMEM_G (3*STB)                // 98304 -> 2 CTAs/SM co-residency

// ============================================================================
// GEMM-H (fp16, cp.async 3-stage pipeline, tile 128x128, 2 CTA/SM)
// Linear CTA raster (n fastest) — best measured config (R13).
// LAYOUT: 0 = fp32 o0[r*ldc+c]
//         3 = merged QKV -> fp16 q(o0)/k(o1)/V^T(o2) head layouts
//         4 = fp16 o0[r*ldc+c]
// ============================================================================
template<int LAYOUT, bool HAS_BIAS, bool HAS_RES>
__global__ void __launch_bounds__(256) gemm_h(
    const __half* __restrict__ A, const __half* __restrict__ W, int K,
    const float* __restrict__ s, const float* __restrict__ bias,
    const float* __restrict__ res, void* __restrict__ o0,
    void* __restrict__ o1, void* __restrict__ o2, int ldc)
{
    extern __shared__ char smem[];
    const uint32_t sb = smem_u32(smem);
    const int tid = threadIdx.x, lane = tid & 31, w = tid >> 5;
    const int wm = w & 1, wn = w >> 1;
    const int m0 = blockIdx.y * 128, n0 = blockIdx.x * 128;
    const int KB = K >> 6;

    const __half* Ag = A + (long)m0 * K;
    const __half* Bg = W + (long)n0 * K;

    const int lr = tid >> 3, lj = tid & 7;

    auto load_stage = [&](int st, int kb) {
        const __half* a = Ag + kb * 64;
        const __half* b = Bg + kb * 64;
        #pragma unroll
        for (int i = 0; i < 4; i++) {
            int r = lr + i * 32;
            uint32_t dsw = r * 128 + ((lj ^ (r & 7)) * 16);
            cp16(sb + st * STB + dsw, a + (long)r * K + lj * 8);
        }
        #pragma unroll
        for (int i = 0; i < 4; i++) {
            int r = lr + i * 32;
            uint32_t dsw = r * 128 + ((lj ^ (r & 7)) * 16);
            cp16(sb + st * STB + 16384 + dsw, b + (long)r * K + lj * 8);
        }
        asm volatile("cp.async.commit_group;" ::: "memory");
    };

    float acc[4][4][4];
    #pragma unroll
    for (int i = 0; i < 4; i++)
        #pragma unroll
        for (int j = 0; j < 4; j++)
            #pragma unroll
            for (int e = 0; e < 4; e++) acc[i][j][e] = 0.f;

    load_stage(0, 0);
    if (KB > 1) load_stage(1, 1);

    for (int kb = 0; kb < KB; kb++) {
        const int st = kb % 3;
        if (kb + 1 < KB) { asm volatile("cp.async.wait_group 1;" ::: "memory"); }
        else             { asm volatile("cp.async.wait_group 0;" ::: "memory"); }
        __syncthreads();
        if (kb + 2 < KB) load_stage((kb + 2) % 3, kb + 2);

        const uint32_t aB = sb + st * STB, bB = sb + st * STB + 16384;
        #pragma unroll
        for (int ks = 0; ks < 4; ks++) {
            const int kk0 = ks * 16;
            uint32_t af[4][4];
            #pragma unroll
            for (int i = 0; i < 4; i++) {
                int ra = wm * 64 + i * 16 + (lane & 15);
                int kk = kk0 + (lane >> 4) * 8;
                uint32_t ad = aB + ra * 128 + (((kk >> 3) ^ (ra & 7)) * 16);
                ldsm_x4(af[i][0], af[i][1], af[i][2], af[i][3], ad);
            }
            #pragma unroll
            for (int j = 0; j < 4; j++) {
                int rb = wn * 32 + j * 8 + (lane & 7);
                int kk = kk0 + ((lane >> 3) & 1) * 8;
                uint32_t bd = bB + rb * 128 + (((kk >> 3) ^ (rb & 7)) * 16);
                uint32_t b0, b1;
                ldsm_x2(b0, b1, bd);
                #pragma unroll
                for (int i = 0; i < 4; i++)
                    mma16816h(acc[i][j], af[i][0], af[i][1], af[i][2], af[i][3], b0, b1);
            }
        }
    }

    // --- epilogue ---
    const int gr = lane >> 2, gc = (lane & 3) * 2;
    #pragma unroll
    for (int i = 0; i < 4; i++) {
        #pragma unroll
        for (int j = 0; j < 4; j++) {
            int rbase = m0 + wm * 64 + i * 16 + gr;
            int cbase = n0 + wn * 32 + j * 8 + gc;
            #pragma unroll
            for (int e = 0; e < 4; e++) {
                int r = rbase + (e >> 1) * 8;
                int c = cbase + (e & 1);
                float v = acc[i][j][e] * s[c];
                if (HAS_BIAS) v += bias[c];
                if (HAS_RES)  v += res[(long)r * D_MODEL + c];
                if (LAYOUT == 0) {
                    ((float*)o0)[(long)r * ldc + c] = v;
                } else if (LAYOUT == 4) {
                    ((__half*)o0)[(long)r * ldc + c] = __float2half_rn(v);
                } else {
                    int b = r >> 10, t = r & 1023;
                    int mat = c >> 11, cc = c & 2047;
                    int h = cc >> 7, d = cc & 127;
                    long base = (long)(b * N_HEADS + h) * (TT * DH);
                    long idx = base + ((mat == 2) ? ((long)d * TT + t) : ((long)t * DH + d));
                    __half* o = (mat == 0) ? (__half*)o0 : ((mat == 1) ? (__half*)o1 : (__half*)o2);
                    o[idx] = __float2half_rn(v);
                }
            }
        }
    }
}

// ============================================================================
// Flash attention v2: 8 warps x 16 q-rows, full key width per warp.
// P stays in registers; softmax warp-local (shfl only).
// ============================================================================
#define FA_RSB 272
#define FA_Q   0
#define FA_K0  34816
#define FA_K1  69632
#define FA_V   104448
#define SMEM_FA 139264

__global__ void __launch_bounds__(256) flash_attn(
    const __half* __restrict__ qh, const __half* __restrict__ kh,
    const __half* __restrict__ vth, __half* __restrict__ ath)
{
    extern __shared__ char smem[];
    const uint32_t sb = smem_u32(smem);
    const int tid = threadIdx.x, lane = tid & 31, w = tid >> 5;
    const int gr = lane >> 2, gc = (lane & 3) * 2;
    const int qt = blockIdx.x, z = blockIdx.y;

    const __half* Qg = qh  + (long)z * TT * DH + (long)qt * 128 * DH;
    const __half* Kg = kh  + (long)z * TT * DH;
    const __half* Vg = vth + (long)z * TT * DH;

    auto load_tile = [&](uint32_t off, const __half* src, int ldg) {
        #pragma unroll
        for (int i = 0; i < 8; i++) {
            int c = tid + i * 256;
            int r = c >> 4, ch = c & 15;
            cp16(sb + off + r * FA_RSB + ch * 16, src + (long)r * ldg + ch * 8);
        }
        asm volatile("cp.async.commit_group;" ::: "memory");
    };

    load_tile(FA_Q, Qg, DH);
    load_tile(FA_K0, Kg, DH);

    float oacc[16][4];
    float m2[2], l2[2];
    #pragma unroll
    for (int j = 0; j < 16; j++)
        #pragma unroll
        for (int e = 0; e < 4; e++) oacc[j][e] = 0.f;
    m2[0] = m2[1] = -1e30f;
    l2[0] = l2[1] = 0.f;

    const int ra = w * 16 + (lane & 15);

    for (int kt = 0; kt < 8; kt++) {
        __syncthreads();
        load_tile(FA_V, Vg + kt * 128, TT);
        if (kt < 7) load_tile((kt & 1) ? FA_K0 : FA_K1, Kg + (long)(kt + 1) * 128 * DH, DH);
        if (kt < 7) { asm volatile("cp.async.wait_group 1;" ::: "memory"); }
        else        { asm volatile("cp.async.wait_group 0;" ::: "memory"); }
        __syncthreads();

        const uint32_t kOff = sb + ((kt & 1) ? FA_K1 : FA_K0);
        float sacc[16][4];
        #pragma unroll
        for (int j = 0; j < 16; j++)
            #pragma unroll
            for (int e = 0; e < 4; e++) sacc[j][e] = 0.f;
        #pragma unroll
        for (int ks = 0; ks < 8; ks++) {
            const int kk = ks * 16 + (lane >> 4) * 8;
            uint32_t a0, a1, a2, a3;
            ldsm_x4(a0, a1, a2, a3, sb + FA_Q + ra * FA_RSB + kk * 2);
            #pragma unroll
            for (int jj = 0; jj < 8; jj++) {
                uint32_t r0, r1, r2, r3;
                ldsm_x4(r0, r1, r2, r3, kOff + (jj * 16 + (lane & 15)) * FA_RSB + kk * 2);
                mma16816h(sacc[2 * jj],     a0, a1, a2, a3, r0, r2);
                mma16816h(sacc[2 * jj + 1], a0, a1, a2, a3, r1, r3);
            }
        }
        #pragma unroll
        for (int j = 0; j < 16; j++)
            #pragma unroll
            for (int e = 0; e < 4; e++) sacc[j][e] *= 0.08838834764831845f;

        float tmx[2];
        tmx[0] = -1e30f; tmx[1] = -1e30f;
        #pragma unroll
        for (int j = 0; j < 16; j++) {
            tmx[0] = fmaxf(tmx[0], fmaxf(sacc[j][0], sacc[j][1]));
            tmx[1] = fmaxf(tmx[1], fmaxf(sacc[j][2], sacc[j][3]));
        }
        #pragma unroll
        for (int s = 0; s < 2; s++) {
            tmx[s] = fmaxf(tmx[s], __shfl_xor_sync(0xffffffffu, tmx[s], 1));
            tmx[s] = fmaxf(tmx[s], __shfl_xor_sync(0xffffffffu, tmx[s], 2));
        }
        float f2[2];
        #pragma unroll
        for (int s = 0; s < 2; s++) {
            float mn = fmaxf(m2[s], tmx[s]);
            f2[s] = __expf(m2[s] - mn);
            m2[s] = mn;
        }
        float tsm[2];
        tsm[0] = 0.f; tsm[1] = 0.f;
        #pragma unroll
        for (int j = 0; j < 16; j++) {
            float p0 = __expf(sacc[j][0] - m2[0]);
            float p1 = __expf(sacc[j][1] - m2[0]);
            float p2 = __expf(sacc[j][2] - m2[1]);
            float p3 = __expf(sacc[j][3] - m2[1]);
            sacc[j][0] = p0; sacc[j][1] = p1; sacc[j][2] = p2; sacc[j][3] = p3;
            tsm[0] += p0 + p1;
            tsm[1] += p2 + p3;
        }
        #pragma unroll
        for (int s = 0; s < 2; s++) {
            tsm[s] += __shfl_xor_sync(0xffffffffu, tsm[s], 1);
            tsm[s] += __shfl_xor_sync(0xffffffffu, tsm[s], 2);
            l2[s] = l2[s] * f2[s] + tsm[s];
        }
        #pragma unroll
        for (int j = 0; j < 16; j++) {
            oacc[j][0] *= f2[0]; oacc[j][1] *= f2[0];
            oacc[j][2] *= f2[1]; oacc[j][3] *= f2[1];
        }

        uint32_t pf[8][4];
        #pragma unroll
        for (int ks = 0; ks < 8; ks++) {
            __half2 h0 = __floats2half2_rn(sacc[2 * ks][0],     sacc[2 * ks][1]);
            __half2 h1 = __floats2half2_rn(sacc[2 * ks][2],     sacc[2 * ks][3]);
            __half2 h2 = __floats2half2_rn(sacc[2 * ks + 1][0], sacc[2 * ks + 1][1]);
            __half2 h3 = __floats2half2_rn(sacc[2 * ks + 1][2], sacc[2 * ks + 1][3]);
            pf[ks][0] = *(uint32_t*)&h0;
            pf[ks][1] = *(uint32_t*)&h1;
            pf[ks][2] = *(uint32_t*)&h2;
            pf[ks][3] = *(uint32_t*)&h3;
        }

        #pragma unroll
        for (int ks = 0; ks < 8; ks++) {
            const int kk = ks * 16 + (lane >> 4) * 8;
            #pragma unroll
            for (int jj = 0; jj < 8; jj++) {
                uint32_t r0, r1, r2, r3;
                ldsm_x4(r0, r1, r2, r3, sb + FA_V + (jj * 16 + (lane & 15)) * FA_RSB + kk * 2);
                mma16816h(oacc[2 * jj],     pf[ks][0], pf[ks][1], pf[ks][2], pf[ks][3], r0, r2);
                mma16816h(oacc[2 * jj + 1], pf[ks][0], pf[ks][1], pf[ks][2], pf[ks][3], r1, r3);
            }
        }
    }

    float inv2[2];
    inv2[0] = 1.0f / l2[0];
    inv2[1] = 1.0f / l2[1];
    const int b = z >> 4, hh = z & 15;
    #pragma unroll
    for (int j = 0; j < 16; j++)
        #pragma unroll
        for (int e = 0; e < 4; e++) {
            int s = e >> 1;
            int t = qt * 128 + w * 16 + gr + s * 8;
            int d = j * 8 + gc + (e & 1);
            ath[((long)(b * TT + t)) * D_MODEL + hh * DH + d] =
                __float2half_rn(oacc[j][e] * inv2[s]);
        }
}

// ---------------- reductions ----------------
__device__ __forceinline__ float warp_sum(float v) {
    #pragma unroll
    for (int o = 16; o; o >>= 1) v += __shfl_xor_sync(0xffffffffu, v, o);
    return v;
}
template<int NW>
__device__ __forceinline__ float block_sum(float v, float* buf) {
    int tid = threadIdx.x;
    v = warp_sum(v);
    __syncthreads();
    if ((tid & 31) == 0) buf[tid >> 5] = v;
    __syncthreads();
    if (tid == 0) { float t = 0; for (int i = 0; i < NW; i++) t += buf[i]; buf[0] = t; }
    __syncthreads();
    return buf[0];
}

// in-register butterfly over NB low bits of the register index
template<int NR, int NB>
__device__ __forceinline__ void reg_butterfly(float* v) {
    #pragma unroll
    for (int b = 0; b < NB; b++) {
        int hb = 1 << b;
        #pragma unroll
        for (int j = 0; j < NR; j++) {
            if (!(j & hb)) {
                float a = v[j], c = v[j | hb];
                v[j] = a + c;
                v[j | hb] = a - c;
            }
        }
    }
}
// shfl butterfly over lane bits 0..4
template<int NR>
__device__ __forceinline__ void shfl_butterfly(float* v, int lane) {
    #pragma unroll
    for (int m = 1; m <= 16; m <<= 1) {
        #pragma unroll
        for (int j = 0; j < NR; j++) {
            float other = __shfl_xor_sync(0xffffffffu, v[j], m);
            v[j] = (lane & m) ? (other - v[j]) : (v[j] + other);
        }
    }
}

// ------- LN (optional) + Hadamard-2048 -> fp16 (register/shfl butterfly) -------
template<bool DO_LN, typename TIN>
__global__ void __launch_bounds__(256) ln_had2048(
    const TIN* __restrict__ in, const float* __restrict__ g,
    const float* __restrict__ bta, __half* __restrict__ outs)
{
    __shared__ float s[2048];
    __shared__ float red[8];
    const int tid = threadIdx.x, lane = tid & 31, w = tid >> 5;
    const TIN* x = in + (long)blockIdx.x * 2048;
    float loc[8];
    #pragma unroll
    for (int j = 0; j < 8; j++) loc[j] = (float)x[tid + 256 * j];

    if (DO_LN) {
        float sm = 0.f, sq = 0.f;
        #pragma unroll
        for (int j = 0; j < 8; j++) { sm += loc[j]; sq += loc[j] * loc[j]; }
        float S  = block_sum<8>(sm, red);
        float SQ = block_sum<8>(sq, red);
        float mu = S * (1.0f / 2048.0f);
        float var = SQ * (1.0f / 2048.0f) - mu * mu;
        float inv = rsqrtf(var + 1e-5f);
        #pragma unroll
        for (int j = 0; j < 8; j++) {
            int c = tid + 256 * j;
            loc[j] = (loc[j] - mu) * inv * g[c] + bta[c];
        }
    }

    reg_butterfly<8, 3>(loc);            // bits 8-10
    #pragma unroll
    for (int j = 0; j < 8; j++) s[tid + 256 * j] = loc[j];
    __syncthreads();
    float v[8];
    #pragma unroll
    for (int jj = 0; jj < 8; jj++) v[jj] = s[lane + 32 * jj + 256 * w];
    reg_butterfly<8, 3>(v);              // bits 5-7
    shfl_butterfly<8>(v, lane);          // bits 0-4

    __half* o = outs + (long)blockIdx.x * 2048;
    #pragma unroll
    for (int jj = 0; jj < 8; jj++)
        o[lane + 32 * jj + 256 * w] = __float2half_rn(v[jj] * 0.022097086912079608f);
}

// ------- GELU(exact) + Hadamard-8192 (fp16 in) -> fp16 (register/shfl) -------
__global__ void __launch_bounds__(512) gelu_had8192(const __half* __restrict__ in, __half* __restrict__ outs)
{
    __shared__ float s[8192];
    const int tid = threadIdx.x, lane = tid & 31, w = tid >> 5;
    const __half* x = in + (long)blockIdx.x * 8192;
    float loc[16];
    #pragma unroll
    for (int j = 0; j < 16; j++) {
        float v = (float)x[tid + 512 * j];
        loc[j] = 0.5f * v * (1.0f + erff(v * 0.7071067811865476f));
    }

    reg_butterfly<16, 4>(loc);           // bits 9-12
    #pragma unroll
    for (int j = 0; j < 16; j++) s[tid + 512 * j] = loc[j];
    __syncthreads();
    float v[16];
    #pragma unroll
    for (int jj = 0; jj < 16; jj++) v[jj] = s[lane + 32 * jj + 512 * w];
    reg_butterfly<16, 4>(v);             // bits 5-8
    shfl_butterfly<16>(v, lane);         // bits 0-4

    __half* o = outs + (long)blockIdx.x * 8192;
    #pragma unroll
    for (int jj = 0; jj < 16; jj++)
        o[lane + 32 * jj + 512 * w] = __float2half_rn(v[jj] * 0.011048543456039806f);
}

// ============================================================================
extern "C" void kernel_launch(void* const* d_in, const int* in_sizes, int n_in,
                              void* d_out, int out_size)
{
    const float*  x    = (const float*) d_in[0];
    const float*  ln1g = (const float*) d_in[1];
    const float*  ln1b = (const float*) d_in[2];
    const float*  ln2g = (const float*) d_in[3];
    const float*  ln2b = (const float*) d_in[4];
    const void*   Qq   = d_in[5];
    const float*  sq   = (const float*) d_in[6];
    const void*   Qk   = d_in[7];
    const float*  sk   = (const float*) d_in[8];
    const void*   Qv   = d_in[9];
    const float*  sv   = (const float*) d_in[10];
    const void*   Qo   = d_in[11];
    const float*  so   = (const float*) d_in[12];
    const void*   Qf1  = d_in[13];
    const float*  sf1  = (const float*) d_in[14];
    const float*  bf1  = (const float*) d_in[15];
    const void*   Qf2  = d_in[16];
    const float*  sf2  = (const float*) d_in[17];
    const float*  bf2  = (const float*) d_in[18];
    float* out = (float*)d_out;

    float *x1, *s6;
    __half *hd, *hf, *ffa, *qh, *kh, *vth, *ath, *wb;
    cudaGetSymbolAddress((void**)&x1,  g_x1);
    cudaGetSymbolAddress((void**)&s6,  g_s6);
    cudaGetSymbolAddress((void**)&hd,  g_hd);
    cudaGetSymbolAddress((void**)&hf,  g_hf);
    cudaGetSymbolAddress((void**)&ffa, g_ffa);
    cudaGetSymbolAddress((void**)&qh,  g_qh);
    cudaGetSymbolAddress((void**)&kh,  g_kh);
    cudaGetSymbolAddress((void**)&vth, g_vth);
    cudaGetSymbolAddress((void**)&ath, g_ath);
    cudaGetSymbolAddress((void**)&wb,  g_w);

    __half* wqkv = wb;                 // q,k,v contiguous (3*NWD)
    __half* wo   = wb + 3 * NWD;       // o,f1,f2 contiguous (NWD + 2*NWF)
    __half* wf1  = wb + 4 * NWD;
    __half* wf2  = wb + 4 * NWD + NWF;

    cudaFuncSetAttribute((const void*)gemm_h<3, false, false>, cudaFuncAttributeMaxDynamicSharedMemorySize, SMEM_G);
    cudaFuncSetAttribute((const void*)gemm_h<0, false, true>,  cudaFuncAttributeMaxDynamicSharedMemorySize, SMEM_G);
    cudaFuncSetAttribute((const void*)gemm_h<4, true, false>,  cudaFuncAttributeMaxDynamicSharedMemorySize, SMEM_G);
    cudaFuncSetAttribute((const void*)gemm_h<0, true, true>,   cudaFuncAttributeMaxDynamicSharedMemorySize, SMEM_G);
    cudaFuncSetAttribute((const void*)flash_attn,              cudaFuncAttributeMaxDynamicSharedMemorySize, SMEM_FA);

    // dtype probe + weight conversion (front-loaded, 2 launches)
    zero_counters<<<1, 1>>>();
    probe_dtype<<<1024, 256>>>(Qq, 1 << 18);
    convert_w3<<<(int)((3 * (NWD / 4) + 255) / 256), 256>>>(Qq, Qk, Qv, wqkv, NWD / 4);
    convert_rest<<<(int)(((NWD / 4 + 2 * (NWF / 4)) + 255) / 256), 256>>>(Qo, Qf1, Qf2, wo, NWD / 4, NWF / 4);
    cat_scales<<<24, 256>>>(sq, sk, sv, s6);
    // LN1 + Hadamard -> fp16
    ln_had2048<true, float><<<BT, 256>>>(x, ln1g, ln1b, hd);
    // merged QKV projection (N=6144, tile 128x128, 2 CTA/SM)
    gemm_h<3, false, false><<<dim3(48, 32), 256, SMEM_G>>>(hd, wqkv, D_MODEL, s6, nullptr, nullptr, qh, kh, vth, 0);
    // fused attention (scores + softmax + P@V), register-P
    flash_attn<<<dim3(8, BH), 256, SMEM_FA>>>(qh, kh, vth, ath);
    // Hadamard(attn fp16) -> fp16
    ln_had2048<false, __half><<<BT, 256>>>(ath, nullptr, nullptr, hd);
    // O-proj (x1 = x + O-proj), fp32 out
    gemm_h<0, false, true><<<dim3(16, 32), 256, SMEM_G>>>(hd, wo, D_MODEL, so, nullptr, x, x1, nullptr, nullptr, D_MODEL);
    // LN2 + Hadamard -> fp16
    ln_had2048<true, float><<<BT, 256>>>(x1, ln2g, ln2b, hd);
    // FF1 -> fp16 pre-activations
    gemm_h<4, true, false><<<dim3(64, 32), 256, SMEM_G>>>(hd, wf1, D_MODEL, sf1, bf1, nullptr, ffa, nullptr, nullptr, D_FF);
    // GELU + Hadamard-8192 -> fp16
    gelu_had8192<<<BT, 512>>>(ffa, hf);
    // FF2 (out = x1 + FF2), fp32 out
    gemm_h<0, true, true><<<dim3(16, 32), 256, SMEM_G>>>(hf, wf2, D_FF, sf2, bf2, x1, out, nullptr, nullptr, D_MODEL);
}